// round 14
// baseline (speedup 1.0000x reference)
#include <cuda_runtime.h>
#include <cuda_fp16.h>

// LightGCN, y-space formulation with fp16 intermediates.
//   y_k = dinv ⊙ x_k  (y0 = dinv ⊙ emb)
//   S[s]     = sum_{e: src=s} y_k[dst(e)]
//   x_{k+1}  = dinv ⊙ S          y_{k+1} = dinv^2 ⊙ S
//   out = (emb + x1 + x2 + x3)/4, emb term exact fp32,
//         x1 = sqrt(deg) * y1, x2 = sqrt(deg) * y2.
//
// SpMM uses paired-edge Half8 gathers: lane owns 8 dims (16B), 16 lanes
// cover a row, so one LDG.128 fetches two edges (even edge -> lanes 0-15,
// odd edge -> lanes 16-31); shfl_xor(16) merges the parities at the end.

#define D 128
#define MAX_NODES 160000
#define MAX_EDGES 2200000
#define SCAN_BLK 1024

struct __align__(8) Half4 {
    __half2 h01;
    __half2 h23;
};

struct __align__(16) Half8 {
    __half2 h0, h1, h2, h3;
};

__device__ int   g_deg[MAX_NODES];          // zeroed at load; self-zeroed in scan23
__device__ int   g_rowptr[MAX_NODES + 1];
__device__ int   g_cursor[MAX_NODES];
__device__ float g_dinv[MAX_NODES];
__device__ float g_rinv[MAX_NODES];         // sqrt(deg) (0 if deg==0)
__device__ int   g_cols[MAX_EDGES];
__device__ Half4 g_y0[(size_t)MAX_NODES * 32];
__device__ Half4 g_y1[(size_t)MAX_NODES * 32];
__device__ Half4 g_y2[(size_t)MAX_NODES * 32];
__device__ int   g_bsum[256];

// ---------------------------------------------------------------- setup ----

// degree histogram, 4 edges per thread; return value DISCARDED (REDG)
__global__ void hist_kernel(const int* __restrict__ src, int nE) {
    int t = blockIdx.x * blockDim.x + threadIdx.x;
    int e = t * 4;
    if (e + 3 < nE) {
        int4 s4 = __ldg((const int4*)(src + e));
        atomicAdd(&g_deg[s4.x], 1);
        atomicAdd(&g_deg[s4.y], 1);
        atomicAdd(&g_deg[s4.z], 1);
        atomicAdd(&g_deg[s4.w], 1);
    } else {
        for (int k = e; k < nE; k++) atomicAdd(&g_deg[src[k]], 1);
    }
}

// per-1024-block exclusive scan of g_deg into g_rowptr; block sums to g_bsum
__global__ void scan1_kernel(int n) {
    __shared__ int sh[SCAN_BLK];
    int tid = threadIdx.x;
    int i = blockIdx.x * SCAN_BLK + tid;
    int v = (i < n) ? g_deg[i] : 0;
    sh[tid] = v;
    __syncthreads();
    for (int off = 1; off < SCAN_BLK; off <<= 1) {
        int t = (tid >= off) ? sh[tid - off] : 0;
        __syncthreads();
        sh[tid] += t;
        __syncthreads();
    }
    if (i < n) g_rowptr[i] = sh[tid] - v;
    if (tid == SCAN_BLK - 1) g_bsum[blockIdx.x] = sh[tid];
}

// merged scan2+scan3: block-prefix + cursor init + dinv/rinv; self-zero g_deg
__global__ void scan23_kernel(int n, int nb) {
    __shared__ int sh[256];
    int tid = threadIdx.x;
    int i = blockIdx.x * 256 + tid;
    int chunk = (blockIdx.x * 256) >> 10;          // same for whole block

    int b = (tid < nb) ? g_bsum[tid] : 0;

    sh[tid] = (tid < chunk) ? b : 0;
    __syncthreads();
    for (int off = 128; off > 0; off >>= 1) {
        if (tid < off) sh[tid] += sh[tid + off];
        __syncthreads();
    }
    int prefix = sh[0];
    __syncthreads();

    sh[tid] = b;
    __syncthreads();
    for (int off = 128; off > 0; off >>= 1) {
        if (tid < off) sh[tid] += sh[tid + off];
        __syncthreads();
    }
    int total = sh[0];

    if (i < n) {
        int rp = g_rowptr[i] + prefix;
        g_rowptr[i] = rp;
        g_cursor[i] = rp;
        int d = g_deg[i];
        float fd = (float)d;
        g_dinv[i] = (d > 0) ? rsqrtf(fd) : 0.0f;
        g_rinv[i] = (d > 0) ? sqrtf(fd) : 0.0f;
        g_deg[i] = 0;                                // ready for next replay
    }
    if (i == 0) g_rowptr[n] = total;
}

// scatter + y0 convert with DISJOINT thread ranges (R8 layout):
//   threads [0, nscat)   : 4 edges each (int4), independent atomics
//   threads [nscat, ...) : one Half4 convert each
__global__ void scatcvt_kernel(const float* __restrict__ uw,
                               const float* __restrict__ iw,
                               const int* __restrict__ src,
                               const int* __restrict__ dst,
                               int nE, int nscat, int num_users, int n_nodes) {
    int i = blockIdx.x * blockDim.x + threadIdx.x;

    if (i < nscat) {
        int e = i * 4;
        if (e + 3 < nE) {
            int4 s4 = __ldg((const int4*)(src + e));
            int4 d4 = __ldg((const int4*)(dst + e));
            int p0 = atomicAdd(&g_cursor[s4.x], 1);
            int p1 = atomicAdd(&g_cursor[s4.y], 1);
            int p2 = atomicAdd(&g_cursor[s4.z], 1);
            int p3 = atomicAdd(&g_cursor[s4.w], 1);
            g_cols[p0] = d4.x;
            g_cols[p1] = d4.y;
            g_cols[p2] = d4.z;
            g_cols[p3] = d4.w;
        } else {
            for (int k = e; k < nE; k++) {
                int pos = atomicAdd(&g_cursor[src[k]], 1);
                g_cols[pos] = dst[k];
            }
        }
        return;
    }

    int j = i - nscat;
    if (j >= n_nodes * 32) return;
    int node = j >> 5, lane = j & 31;
    const float4* srcp = (const float4*)((node < num_users)
                            ? uw + (size_t)node * D
                            : iw + (size_t)(node - num_users) * D);
    float4 f = srcp[lane];
    float dv = g_dinv[node];
    Half4 r;
    r.h01 = __floats2half2_rn(f.x * dv, f.y * dv);
    r.h23 = __floats2half2_rn(f.z * dv, f.w * dv);
    g_y0[j] = r;
}

// ----------------------------------------------------------------- SpMM ----
// Paired-edge gather: lane owns 8 dims (one Half8 = 16B at Half4 index
// (lane&15)*2 of the row). Lanes 0-15 take even edges, 16-31 odd edges.
// shfl_xor(16) merges the two parities at the end.

__device__ __forceinline__ void acc8(const Half8& v, float* a) {
    float2 f0 = __half22float2(v.h0);
    float2 f1 = __half22float2(v.h1);
    float2 f2 = __half22float2(v.h2);
    float2 f3 = __half22float2(v.h3);
    a[0] += f0.x; a[1] += f0.y;
    a[2] += f1.x; a[3] += f1.y;
    a[4] += f2.x; a[5] += f2.y;
    a[6] += f3.x; a[7] += f3.y;
}

__device__ __forceinline__ void gather_row_pair(const Half4* __restrict__ xin,
                                                int start, int end,
                                                bool lo, int h4, float* a) {
    int j = start;
    // 4 pairs = 8 edges per iteration
    for (; j + 8 <= end; j += 8) {
        int c0 = __ldg(&g_cols[j]);
        int c1 = __ldg(&g_cols[j + 1]);
        int c2 = __ldg(&g_cols[j + 2]);
        int c3 = __ldg(&g_cols[j + 3]);
        int c4 = __ldg(&g_cols[j + 4]);
        int c5 = __ldg(&g_cols[j + 5]);
        int c6 = __ldg(&g_cols[j + 6]);
        int c7 = __ldg(&g_cols[j + 7]);
        int m0 = lo ? c0 : c1;
        int m1 = lo ? c2 : c3;
        int m2 = lo ? c4 : c5;
        int m3 = lo ? c6 : c7;
        Half8 v0 = *(const Half8*)(xin + (size_t)m0 * 32 + h4);
        Half8 v1 = *(const Half8*)(xin + (size_t)m1 * 32 + h4);
        Half8 v2 = *(const Half8*)(xin + (size_t)m2 * 32 + h4);
        Half8 v3 = *(const Half8*)(xin + (size_t)m3 * 32 + h4);
        acc8(v0, a);
        acc8(v1, a);
        acc8(v2, a);
        acc8(v3, a);
    }
    // remaining pairs
    for (; j + 2 <= end; j += 2) {
        int c0 = __ldg(&g_cols[j]);
        int c1 = __ldg(&g_cols[j + 1]);
        int m = lo ? c0 : c1;
        Half8 v = *(const Half8*)(xin + (size_t)m * 32 + h4);
        acc8(v, a);
    }
    // odd single edge: lower half only
    if (j < end) {
        if (lo) {
            int c = __ldg(&g_cols[j]);
            Half8 v = *(const Half8*)(xin + (size_t)c * 32 + h4);
            acc8(v, a);
        }
    }
    // merge even/odd parities
#pragma unroll
    for (int k = 0; k < 8; k++)
        a[k] += __shfl_xor_sync(0xffffffffu, a[k], 16);
}

// layers 1 & 2: gather y_{k-1} -> write y_k = dinv^2 * sum
__global__ void __launch_bounds__(256)
spmm_mid(int layer, int n_nodes) {
    int warp = (blockIdx.x * blockDim.x + threadIdx.x) >> 5;
    int lane = threadIdx.x & 31;
    if (warp >= n_nodes) return;

    const Half4* xin  = (layer == 1) ? g_y0 : g_y1;
    Half4*       xout = (layer == 1) ? g_y1 : g_y2;

    bool lo = lane < 16;
    int h4 = (lane & 15) * 2;

    float dv = g_dinv[warp];
    float w2 = dv * dv;
    int start = __ldg(&g_rowptr[warp]);
    int end   = __ldg(&g_rowptr[warp + 1]);

    float a[8] = {0.f, 0.f, 0.f, 0.f, 0.f, 0.f, 0.f, 0.f};
    gather_row_pair(xin, start, end, lo, h4, a);

    if (lo) {
        Half8 r;
        r.h0 = __floats2half2_rn(a[0] * w2, a[1] * w2);
        r.h1 = __floats2half2_rn(a[2] * w2, a[3] * w2);
        r.h2 = __floats2half2_rn(a[4] * w2, a[5] * w2);
        r.h3 = __floats2half2_rn(a[6] * w2, a[7] * w2);
        *(Half8*)(xout + (size_t)warp * 32 + h4) = r;
    }
}

// layer 3: gather y2 -> x3 = dinv*sum; fuse out = (emb + x1 + x2 + x3)/4
// with x1 = rinv*y1, x2 = rinv*y2. Own-row loads hoisted above the gather.
__global__ void __launch_bounds__(256)
spmm_last(const float* __restrict__ uw, const float* __restrict__ iw,
          int num_users, int n_nodes, float* __restrict__ out) {
    int warp = (blockIdx.x * blockDim.x + threadIdx.x) >> 5;
    int lane = threadIdx.x & 31;
    if (warp >= n_nodes) return;

    bool lo = lane < 16;
    int h4 = (lane & 15) * 2;

    float dv = g_dinv[warp];
    float rv = g_rinv[warp];
    int start = __ldg(&g_rowptr[warp]);
    int end   = __ldg(&g_rowptr[warp + 1]);

    // issue own-row loads early; they complete under the gather chain
    Half8 w1 = *(const Half8*)(g_y1 + (size_t)warp * 32 + h4);
    Half8 w2 = *(const Half8*)(g_y2 + (size_t)warp * 32 + h4);
    const float4* ep = (const float4*)((warp < num_users)
                          ? uw + (size_t)warp * D
                          : iw + (size_t)(warp - num_users) * D);
    float4 e0 = ep[h4];
    float4 e1 = ep[h4 + 1];

    float a[8] = {0.f, 0.f, 0.f, 0.f, 0.f, 0.f, 0.f, 0.f};
    gather_row_pair(g_y2, start, end, lo, h4, a);

    if (lo) {
        float2 p0 = __half22float2(w1.h0);
        float2 p1 = __half22float2(w1.h1);
        float2 p2 = __half22float2(w1.h2);
        float2 p3 = __half22float2(w1.h3);
        float2 q0 = __half22float2(w2.h0);
        float2 q1 = __half22float2(w2.h1);
        float2 q2 = __half22float2(w2.h2);
        float2 q3 = __half22float2(w2.h3);

        float4 o0, o1;
        o0.x = (e0.x + rv * (p0.x + q0.x) + dv * a[0]) * 0.25f;
        o0.y = (e0.y + rv * (p0.y + q0.y) + dv * a[1]) * 0.25f;
        o0.z = (e0.z + rv * (p1.x + q1.x) + dv * a[2]) * 0.25f;
        o0.w = (e0.w + rv * (p1.y + q1.y) + dv * a[3]) * 0.25f;
        o1.x = (e1.x + rv * (p2.x + q2.x) + dv * a[4]) * 0.25f;
        o1.y = (e1.y + rv * (p2.y + q2.y) + dv * a[5]) * 0.25f;
        o1.z = (e1.z + rv * (p3.x + q3.x) + dv * a[6]) * 0.25f;
        o1.w = (e1.w + rv * (p3.y + q3.y) + dv * a[7]) * 0.25f;

        float4* op = (float4*)(out + (size_t)warp * D);
        op[h4]     = o0;
        op[h4 + 1] = o1;
    }
}

// --------------------------------------------------------------- launch ----

extern "C" void kernel_launch(void* const* d_in, const int* in_sizes, int n_in,
                              void* d_out, int out_size) {
    const float* uw = (const float*)d_in[0];
    const float* iw = (const float*)d_in[1];
    const int*   ei = (const int*)d_in[2];

    int num_users = in_sizes[0] / D;
    int num_items = in_sizes[1] / D;
    int n_nodes = num_users + num_items;
    int nE = in_sizes[2] / 2;
    const int* src = ei;
    const int* dst = ei + nE;
    float* out = (float*)d_out;

    // CSR build (g_deg arrives zeroed: module init / self-zero in scan23)
    hist_kernel<<<((nE + 3) / 4 + 255) / 256, 256>>>(src, nE);
    int nb = (n_nodes + SCAN_BLK - 1) / SCAN_BLK;
    scan1_kernel<<<nb, SCAN_BLK>>>(n_nodes);
    scan23_kernel<<<(n_nodes + 255) / 256, 256>>>(n_nodes, nb);

    int nscat = (nE + 3) / 4;
    int total_threads = nscat + n_nodes * 32;
    scatcvt_kernel<<<(total_threads + 255) / 256, 256>>>(uw, iw, src, dst, nE,
                                                         nscat, num_users, n_nodes);

    // 3 propagation layers
    int blocks = (n_nodes * 32 + 255) / 256;
    spmm_mid<<<blocks, 256>>>(1, n_nodes);
    spmm_mid<<<blocks, 256>>>(2, n_nodes);
    spmm_last<<<blocks, 256>>>(uw, iw, num_users, n_nodes, out);
}

// round 15
// speedup vs baseline: 1.2042x; 1.2042x over previous
#include <cuda_runtime.h>
#include <cuda_fp16.h>

// LightGCN, y-space formulation with fp16 intermediates.
//   y_k = dinv ⊙ x_k  (y0 = dinv ⊙ emb)
//   S[s]     = sum_{e: src=s} y_k[dst(e)]
//   x_{k+1}  = dinv ⊙ S          y_{k+1} = dinv^2 ⊙ S
//   out = (emb + x1 + x2 + x3)/4, emb term exact fp32,
//         x1 = sqrt(deg) * y1, x2 = sqrt(deg) * y2.
//
// Structure = R13 (best measured). Gather keeps the whole-warp-per-row
// Half4 pattern (R14 lesson: paired-row LDG.128 gathers fragment L1tex
// wavefronts) with a 16-edge unroll for MLP.

#define D 128
#define MAX_NODES 160000
#define MAX_EDGES 2200000
#define SCAN_BLK 1024

struct __align__(8) Half4 {
    __half2 h01;
    __half2 h23;
};

__device__ int   g_deg[MAX_NODES];          // zeroed at load; self-zeroed in scan23
__device__ int   g_rowptr[MAX_NODES + 1];
__device__ int   g_cursor[MAX_NODES];
__device__ float g_dinv[MAX_NODES];
__device__ float g_rinv[MAX_NODES];         // sqrt(deg) (0 if deg==0)
__device__ int   g_cols[MAX_EDGES];
__device__ Half4 g_y0[(size_t)MAX_NODES * 32];
__device__ Half4 g_y1[(size_t)MAX_NODES * 32];
__device__ Half4 g_y2[(size_t)MAX_NODES * 32];
__device__ int   g_bsum[256];

// ---------------------------------------------------------------- setup ----

// degree histogram, 4 edges per thread; return value DISCARDED (REDG)
__global__ void hist_kernel(const int* __restrict__ src, int nE) {
    int t = blockIdx.x * blockDim.x + threadIdx.x;
    int e = t * 4;
    if (e + 3 < nE) {
        int4 s4 = __ldg((const int4*)(src + e));
        atomicAdd(&g_deg[s4.x], 1);
        atomicAdd(&g_deg[s4.y], 1);
        atomicAdd(&g_deg[s4.z], 1);
        atomicAdd(&g_deg[s4.w], 1);
    } else {
        for (int k = e; k < nE; k++) atomicAdd(&g_deg[src[k]], 1);
    }
}

// per-1024-block exclusive scan of g_deg into g_rowptr; block sums to g_bsum
__global__ void scan1_kernel(int n) {
    __shared__ int sh[SCAN_BLK];
    int tid = threadIdx.x;
    int i = blockIdx.x * SCAN_BLK + tid;
    int v = (i < n) ? g_deg[i] : 0;
    sh[tid] = v;
    __syncthreads();
    for (int off = 1; off < SCAN_BLK; off <<= 1) {
        int t = (tid >= off) ? sh[tid - off] : 0;
        __syncthreads();
        sh[tid] += t;
        __syncthreads();
    }
    if (i < n) g_rowptr[i] = sh[tid] - v;
    if (tid == SCAN_BLK - 1) g_bsum[blockIdx.x] = sh[tid];
}

// merged scan2+scan3: block-prefix + cursor init + dinv/rinv; self-zero g_deg
__global__ void scan23_kernel(int n, int nb) {
    __shared__ int sh[256];
    int tid = threadIdx.x;
    int i = blockIdx.x * 256 + tid;
    int chunk = (blockIdx.x * 256) >> 10;          // same for whole block

    int b = (tid < nb) ? g_bsum[tid] : 0;

    sh[tid] = (tid < chunk) ? b : 0;
    __syncthreads();
    for (int off = 128; off > 0; off >>= 1) {
        if (tid < off) sh[tid] += sh[tid + off];
        __syncthreads();
    }
    int prefix = sh[0];
    __syncthreads();

    sh[tid] = b;
    __syncthreads();
    for (int off = 128; off > 0; off >>= 1) {
        if (tid < off) sh[tid] += sh[tid + off];
        __syncthreads();
    }
    int total = sh[0];

    if (i < n) {
        int rp = g_rowptr[i] + prefix;
        g_rowptr[i] = rp;
        g_cursor[i] = rp;
        int d = g_deg[i];
        float fd = (float)d;
        g_dinv[i] = (d > 0) ? rsqrtf(fd) : 0.0f;
        g_rinv[i] = (d > 0) ? sqrtf(fd) : 0.0f;
        g_deg[i] = 0;                                // ready for next replay
    }
    if (i == 0) g_rowptr[n] = total;
}

// scatter + y0 convert with DISJOINT thread ranges (R8 layout):
//   threads [0, nscat)   : 4 edges each (int4), independent atomics
//   threads [nscat, ...) : one Half4 convert each
__global__ void scatcvt_kernel(const float* __restrict__ uw,
                               const float* __restrict__ iw,
                               const int* __restrict__ src,
                               const int* __restrict__ dst,
                               int nE, int nscat, int num_users, int n_nodes) {
    int i = blockIdx.x * blockDim.x + threadIdx.x;

    if (i < nscat) {
        int e = i * 4;
        if (e + 3 < nE) {
            int4 s4 = __ldg((const int4*)(src + e));
            int4 d4 = __ldg((const int4*)(dst + e));
            int p0 = atomicAdd(&g_cursor[s4.x], 1);
            int p1 = atomicAdd(&g_cursor[s4.y], 1);
            int p2 = atomicAdd(&g_cursor[s4.z], 1);
            int p3 = atomicAdd(&g_cursor[s4.w], 1);
            g_cols[p0] = d4.x;
            g_cols[p1] = d4.y;
            g_cols[p2] = d4.z;
            g_cols[p3] = d4.w;
        } else {
            for (int k = e; k < nE; k++) {
                int pos = atomicAdd(&g_cursor[src[k]], 1);
                g_cols[pos] = dst[k];
            }
        }
        return;
    }

    int j = i - nscat;
    if (j >= n_nodes * 32) return;
    int node = j >> 5, lane = j & 31;
    const float4* srcp = (const float4*)((node < num_users)
                            ? uw + (size_t)node * D
                            : iw + (size_t)(node - num_users) * D);
    float4 f = srcp[lane];
    float dv = g_dinv[node];
    Half4 r;
    r.h01 = __floats2half2_rn(f.x * dv, f.y * dv);
    r.h23 = __floats2half2_rn(f.z * dv, f.w * dv);
    g_y0[j] = r;
}

// ----------------------------------------------------------------- SpMM ----
// One warp per row; lane owns dims [4*lane, 4*lane+4) as one Half4.
// Pure sum over neighbors; 16-edge unroll for MLP against L2 latency.

__device__ __forceinline__ void acc_edge(Half4 r,
                                         float& a0, float& a1, float& a2, float& a3) {
    float2 f01 = __half22float2(r.h01);
    float2 f23 = __half22float2(r.h23);
    a0 += f01.x;
    a1 += f01.y;
    a2 += f23.x;
    a3 += f23.y;
}

__device__ __forceinline__ void gather_row(const Half4* __restrict__ xin,
                                           int start, int end, int lane,
                                           float& a0, float& a1, float& a2, float& a3) {
    int j = start;
    for (; j + 16 <= end; j += 16) {
        int c[16];
#pragma unroll
        for (int k = 0; k < 16; k++) c[k] = __ldg(&g_cols[j + k]);
        Half4 r[16];
#pragma unroll
        for (int k = 0; k < 16; k++) r[k] = xin[(size_t)c[k] * 32 + lane];
#pragma unroll
        for (int k = 0; k < 16; k++) acc_edge(r[k], a0, a1, a2, a3);
    }
    for (; j + 4 <= end; j += 4) {
        int c0 = __ldg(&g_cols[j]);
        int c1 = __ldg(&g_cols[j + 1]);
        int c2 = __ldg(&g_cols[j + 2]);
        int c3 = __ldg(&g_cols[j + 3]);
        Half4 r0 = xin[(size_t)c0 * 32 + lane];
        Half4 r1 = xin[(size_t)c1 * 32 + lane];
        Half4 r2 = xin[(size_t)c2 * 32 + lane];
        Half4 r3 = xin[(size_t)c3 * 32 + lane];
        acc_edge(r0, a0, a1, a2, a3);
        acc_edge(r1, a0, a1, a2, a3);
        acc_edge(r2, a0, a1, a2, a3);
        acc_edge(r3, a0, a1, a2, a3);
    }
    for (; j < end; j++) {
        int c = __ldg(&g_cols[j]);
        Half4 r = xin[(size_t)c * 32 + lane];
        acc_edge(r, a0, a1, a2, a3);
    }
}

// layers 1 & 2: gather y_{k-1} -> write y_k = dinv^2 * sum
__global__ void __launch_bounds__(256)
spmm_mid(int layer, int n_nodes) {
    int warp = (blockIdx.x * blockDim.x + threadIdx.x) >> 5;
    int lane = threadIdx.x & 31;
    if (warp >= n_nodes) return;

    const Half4* xin  = (layer == 1) ? g_y0 : g_y1;
    Half4*       xout = (layer == 1) ? g_y1 : g_y2;

    float dv = g_dinv[warp];
    float w2 = dv * dv;
    int start = __ldg(&g_rowptr[warp]);
    int end   = __ldg(&g_rowptr[warp + 1]);

    float a0 = 0.f, a1 = 0.f, a2 = 0.f, a3 = 0.f;
    gather_row(xin, start, end, lane, a0, a1, a2, a3);

    Half4 r;
    r.h01 = __floats2half2_rn(a0 * w2, a1 * w2);
    r.h23 = __floats2half2_rn(a2 * w2, a3 * w2);
    xout[(size_t)warp * 32 + lane] = r;
}

// layer 3: gather y2 -> x3 = dinv*sum; fuse out = (emb + x1 + x2 + x3)/4
// with x1 = rinv*y1, x2 = rinv*y2. Own-row loads hoisted above the gather.
__global__ void __launch_bounds__(256)
spmm_last(const float* __restrict__ uw, const float* __restrict__ iw,
          int num_users, int n_nodes, float* __restrict__ out) {
    int warp = (blockIdx.x * blockDim.x + threadIdx.x) >> 5;
    int lane = threadIdx.x & 31;
    if (warp >= n_nodes) return;

    float dv = g_dinv[warp];
    float rv = g_rinv[warp];
    int start = __ldg(&g_rowptr[warp]);
    int end   = __ldg(&g_rowptr[warp + 1]);

    // issue own-row loads early; they complete under the gather chain
    Half4 w1 = g_y1[(size_t)warp * 32 + lane];
    Half4 w2 = g_y2[(size_t)warp * 32 + lane];
    const float4* ep = (const float4*)((warp < num_users)
                          ? uw + (size_t)warp * D
                          : iw + (size_t)(warp - num_users) * D);
    float4 e = ep[lane];

    float a0 = 0.f, a1 = 0.f, a2 = 0.f, a3 = 0.f;
    gather_row(g_y2, start, end, lane, a0, a1, a2, a3);
    a0 *= dv; a1 *= dv; a2 *= dv; a3 *= dv;      // x3

    float2 p01 = __half22float2(w1.h01);
    float2 p23 = __half22float2(w1.h23);
    float2 q01 = __half22float2(w2.h01);
    float2 q23 = __half22float2(w2.h23);

    float4 o;
    o.x = (e.x + rv * (p01.x + q01.x) + a0) * 0.25f;
    o.y = (e.y + rv * (p01.y + q01.y) + a1) * 0.25f;
    o.z = (e.z + rv * (p23.x + q23.x) + a2) * 0.25f;
    o.w = (e.w + rv * (p23.y + q23.y) + a3) * 0.25f;
    ((float4*)(out + (size_t)warp * D))[lane] = o;
}

// --------------------------------------------------------------- launch ----

extern "C" void kernel_launch(void* const* d_in, const int* in_sizes, int n_in,
                              void* d_out, int out_size) {
    const float* uw = (const float*)d_in[0];
    const float* iw = (const float*)d_in[1];
    const int*   ei = (const int*)d_in[2];

    int num_users = in_sizes[0] / D;
    int num_items = in_sizes[1] / D;
    int n_nodes = num_users + num_items;
    int nE = in_sizes[2] / 2;
    const int* src = ei;
    const int* dst = ei + nE;
    float* out = (float*)d_out;

    // CSR build (g_deg arrives zeroed: module init / self-zero in scan23)
    hist_kernel<<<((nE + 3) / 4 + 255) / 256, 256>>>(src, nE);
    int nb = (n_nodes + SCAN_BLK - 1) / SCAN_BLK;
    scan1_kernel<<<nb, SCAN_BLK>>>(n_nodes);
    scan23_kernel<<<(n_nodes + 255) / 256, 256>>>(n_nodes, nb);

    int nscat = (nE + 3) / 4;
    int total_threads = nscat + n_nodes * 32;
    scatcvt_kernel<<<(total_threads + 255) / 256, 256>>>(uw, iw, src, dst, nE,
                                                         nscat, num_users, n_nodes);

    // 3 propagation layers
    int blocks = (n_nodes * 32 + 255) / 256;
    spmm_mid<<<blocks, 256>>>(1, n_nodes);
    spmm_mid<<<blocks, 256>>>(2, n_nodes);
    spmm_last<<<blocks, 256>>>(uw, iw, num_users, n_nodes, out);
}